// round 1
// baseline (speedup 1.0000x reference)
#include <cuda_runtime.h>
#include <math.h>
#include <stdint.h>

#define BB 16
#define NN 1024
#define DD 256
#define L2E 1.4426950408889634f

static __device__ float d_logK[BB*NN*NN];   // 64 MB scratch
static __device__ float d_f[BB*NN];
static __device__ float d_g[BB*NN];
static __device__ float d_inx[BB*NN];
static __device__ float d_iny[BB*NN];
static __device__ float d_r[BB*NN];
static __device__ float d_c[BB*NN];
static __device__ float d_Lmain[BB];
static __device__ float d_LbX[BB];
static __device__ float d_LbY[BB];
static __device__ float d_loss[BB];

__device__ __forceinline__ float warpMax(float v){
  #pragma unroll
  for (int o=16;o>0;o>>=1) v = fmaxf(v, __shfl_xor_sync(0xffffffffu, v, o));
  return v;
}
__device__ __forceinline__ float warpSum(float v){
  #pragma unroll
  for (int o=16;o>0;o>>=1) v += __shfl_xor_sync(0xffffffffu, v, o);
  return v;
}
// 256-thread block reductions; return the result to ALL threads.
__device__ __forceinline__ float blockMax256(float v, float* sm){
  __syncthreads();
  v = warpMax(v);
  int w = threadIdx.x>>5, l = threadIdx.x&31;
  if (l==0) sm[w]=v;
  __syncthreads();
  if (w==0){
    float t = (l<8)? sm[l] : -INFINITY;
    t = warpMax(t);
    if (l==0) sm[0]=t;
  }
  __syncthreads();
  return sm[0];
}
__device__ __forceinline__ float blockSum256(float v, float* sm){
  __syncthreads();
  v = warpSum(v);
  int w = threadIdx.x>>5, l = threadIdx.x&31;
  if (l==0) sm[w]=v;
  __syncthreads();
  if (w==0){
    float t = (l<8)? sm[l] : 0.0f;
    t = warpSum(t);
    if (l==0) sm[0]=t;
  }
  __syncthreads();
  return sm[0];
}

// ---------------- init: zero g and loss accumulators (graph replays!) --------
__global__ void k_init(){
  int t = blockIdx.x*256 + threadIdx.x;
  for (int i=t; i<BB*NN; i += gridDim.x*256) d_g[i] = 0.0f;
  if (t < BB){ d_Lmain[t]=0.0f; d_LbX[t]=0.0f; d_LbY[t]=0.0f; }
}

// ---------------- inverse row norms (one warp per row) -----------------------
__global__ void __launch_bounds__(256) k_norms(const float* __restrict__ X, const float* __restrict__ Y){
  int warp = threadIdx.x>>5, lane = threadIdx.x&31;
  int row = blockIdx.x*8 + warp;               // 0..B*N-1
  const float* src = blockIdx.y ? Y : X;
  float* dst = blockIdx.y ? d_iny : d_inx;
  const float* p = src + (size_t)row*DD;
  float4 a = *(const float4*)(p + lane*4);
  float4 c = *(const float4*)(p + 128 + lane*4);
  float ss = a.x*a.x+a.y*a.y+a.z*a.z+a.w*a.w
           + c.x*c.x+c.y*c.y+c.z*c.z+c.w*c.w;
  ss = warpSum(ss);
  if (lane==0) dst[row] = 1.0f / fmaxf(sqrtf(ss), 1e-12f);
}

// ---------------- S = Xn Yn^T -> logK (64x64 tile, 4x4 microtile) ------------
__global__ void __launch_bounds__(256) k_gemm(const float* __restrict__ X, const float* __restrict__ Y){
  __shared__ float As[32][68];
  __shared__ float Bs[32][68];
  int b = blockIdx.z;
  int i0 = blockIdx.y*64, j0 = blockIdx.x*64;
  int tid = threadIdx.x;
  const float* Xp = X + ((size_t)(b*NN + i0))*DD;
  const float* Yp = Y + ((size_t)(b*NN + j0))*DD;
  int lrow = tid>>3, lk4 = (tid&7)*4;
  int tx = tid&15, ty = tid>>4;
  float acc[4][4];
  #pragma unroll
  for (int u=0;u<4;u++)
    #pragma unroll
    for (int w=0;w<4;w++) acc[u][w]=0.0f;

  for (int kc=0; kc<DD; kc+=32){
    #pragma unroll
    for (int h=0;h<2;h++){
      int r = lrow + h*32;
      float4 a = *(const float4*)(Xp + (size_t)r*DD + kc + lk4);
      As[lk4+0][r]=a.x; As[lk4+1][r]=a.y; As[lk4+2][r]=a.z; As[lk4+3][r]=a.w;
      float4 bv = *(const float4*)(Yp + (size_t)r*DD + kc + lk4);
      Bs[lk4+0][r]=bv.x; Bs[lk4+1][r]=bv.y; Bs[lk4+2][r]=bv.z; Bs[lk4+3][r]=bv.w;
    }
    __syncthreads();
    #pragma unroll
    for (int k=0;k<32;k++){
      float4 av = *(const float4*)&As[k][ty*4];
      float4 bv = *(const float4*)&Bs[k][tx*4];
      float a4[4]={av.x,av.y,av.z,av.w};
      float b4[4]={bv.x,bv.y,bv.z,bv.w};
      #pragma unroll
      for (int u=0;u<4;u++)
        #pragma unroll
        for (int w=0;w<4;w++)
          acc[u][w] = fmaf(a4[u], b4[w], acc[u][w]);
    }
    __syncthreads();
  }
  float inx[4], iny[4];
  #pragma unroll
  for (int u=0;u<4;u++){
    inx[u] = d_inx[b*NN + i0 + ty*4 + u];
    iny[u] = d_iny[b*NN + j0 + tx*4 + u];
  }
  #pragma unroll
  for (int u=0;u<4;u++){
    int i = i0 + ty*4 + u;
    float o[4];
    #pragma unroll
    for (int w=0;w<4;w++){
      int j = j0 + tx*4 + w;
      float S = acc[u][w]*inx[u]*iny[w];
      float q = fmaxf(1.0f - S, 0.0f);
      float pj = fabsf((float)(i-j))*(1.0f/1023.0f);
      o[w] = -100.0f*q - 0.2f*pj;          // logK = -C/eps
    }
    *(float4*)(d_logK + ((size_t)(b*NN+i))*NN + j0 + tx*4) = make_float4(o[0],o[1],o[2],o[3]);
  }
}

// ---------------- sinkhorn f-update: f_i = loga - LSE_j(logK[i,:] + g) -------
__global__ void __launch_bounds__(256) k_f(){
  __shared__ float red[32];
  int row = blockIdx.x;                 // = b*NN + i
  int b = row >> 10;
  const float* lk = d_logK + (size_t)row*NN;
  const float* gp = d_g + b*NN;
  int tid = threadIdx.x;
  float4 v  = *(const float4*)(lk + tid*4);
  float4 gv = *(const float4*)(gp + tid*4);
  float x0=v.x+gv.x, x1=v.y+gv.y, x2=v.z+gv.z, x3=v.w+gv.w;
  float m = fmaxf(fmaxf(x0,x1), fmaxf(x2,x3));
  float M = blockMax256(m, red);
  float s = exp2f((x0-M)*L2E) + exp2f((x1-M)*L2E)
          + exp2f((x2-M)*L2E) + exp2f((x3-M)*L2E);
  float S = blockSum256(s, red);
  if (tid==0){
    const float LOGA = logf(1.0f/(float)NN + 1e-12f);
    d_f[row] = LOGA - (M + logf(S));
  }
}

// ---------------- sinkhorn g-update: g_j = logb - LSE_i(logK[:,j] + f) -------
__global__ void __launch_bounds__(256) k_g(){
  __shared__ float fsh[NN];
  __shared__ float msh[4][64];
  __shared__ float ssh[4][64];
  int b = blockIdx.y, j0 = blockIdx.x*64;
  int tid = threadIdx.x;
  for (int i=tid; i<NN; i+=256) fsh[i] = d_f[b*NN + i];
  __syncthreads();
  int jc = tid&63, ir = tid>>6;
  const float* base = d_logK + (size_t)b*NN*NN + j0 + jc;
  float mm[4], ss[4];
  #pragma unroll
  for (int q=0;q<4;q++){ mm[q] = -INFINITY; ss[q] = 0.0f; }
  for (int t=0; t<64; t++){
    #pragma unroll
    for (int q=0;q<4;q++){
      int i = ir + 16*t + 4*q;
      float x = base[(size_t)i*NN] + fsh[i];
      if (x <= mm[q]) { ss[q] += exp2f((x-mm[q])*L2E); }
      else { ss[q] = fmaf(ss[q], exp2f((mm[q]-x)*L2E), 1.0f); mm[q] = x; }  // rare record-break
    }
  }
  float M = fmaxf(fmaxf(mm[0],mm[1]), fmaxf(mm[2],mm[3]));
  float S = ss[0]*exp2f((mm[0]-M)*L2E) + ss[1]*exp2f((mm[1]-M)*L2E)
          + ss[2]*exp2f((mm[2]-M)*L2E) + ss[3]*exp2f((mm[3]-M)*L2E);
  msh[ir][jc] = M; ssh[ir][jc] = S;
  __syncthreads();
  if (ir==0){
    float M0=msh[0][jc], M1=msh[1][jc], M2=msh[2][jc], M3=msh[3][jc];
    float Mt = fmaxf(fmaxf(M0,M1), fmaxf(M2,M3));
    float St = ssh[0][jc]*exp2f((M0-Mt)*L2E) + ssh[1][jc]*exp2f((M1-Mt)*L2E)
             + ssh[2][jc]*exp2f((M2-Mt)*L2E) + ssh[3][jc]*exp2f((M3-Mt)*L2E);
    const float LOGB = logf(1.0f/(float)NN + 1e-12f);
    d_g[b*NN + j0 + jc] = LOGB - (Mt + logf(St));
  }
}

// ------------ row pass: T@Y, r_i, L_main, sum (X - Y_bar)^2 ------------------
__global__ void __launch_bounds__(256) k_rowpass(const float* __restrict__ X, const float* __restrict__ Y){
  __shared__ float gsh[NN];
  __shared__ float Tsh[32][68];
  __shared__ float rsh[32];
  __shared__ float fsh[32];
  __shared__ float red[32];
  int b = blockIdx.y, i0 = blockIdx.x*32;
  int tid = threadIdx.x;
  for (int j=tid; j<NN; j+=256) gsh[j] = d_g[b*NN + j];
  if (tid<32){ rsh[tid]=0.0f; fsh[tid]=d_f[b*NN + i0 + tid]; }
  __syncthreads();
  float acc[32];
  #pragma unroll
  for (int r=0;r<32;r++) acc[r]=0.0f;
  float lmain = 0.0f;
  int lr = tid>>3, lj8 = (tid&7)*8;
  const float* lkb = d_logK + ((size_t)(b*NN + i0))*NN;
  const float* Yp  = Y + ((size_t)b*NN)*DD + tid;

  for (int kc=0; kc<NN; kc+=64){
    float fv = fsh[lr];
    const float* rowp = lkb + (size_t)lr*NN + kc + lj8;
    float4 l0 = *(const float4*)rowp;
    float4 l1 = *(const float4*)(rowp+4);
    float lkv[8] = {l0.x,l0.y,l0.z,l0.w,l1.x,l1.y,l1.z,l1.w};
    float rpart = 0.0f;
    #pragma unroll
    for (int u=0;u<8;u++){
      int j = kc + lj8 + u;
      float t = exp2f((lkv[u] + fv + gsh[j])*L2E);     // T_ij
      Tsh[lr][lj8+u] = t;
      rpart += t;
      float pj = fabsf((float)(i0 + lr - j))*(1.0f/1023.0f);
      lmain = fmaf(t, (-lkv[u] - 0.2f*pj)*0.1f, lmain); // C_content recovered
    }
    atomicAdd(&rsh[lr], rpart);
    __syncthreads();
    #pragma unroll 4
    for (int k=0;k<64;k+=4){
      float yv0 = Yp[(size_t)(kc+k+0)*DD];
      float yv1 = Yp[(size_t)(kc+k+1)*DD];
      float yv2 = Yp[(size_t)(kc+k+2)*DD];
      float yv3 = Yp[(size_t)(kc+k+3)*DD];
      #pragma unroll
      for (int r=0;r<32;r++){
        float4 t4 = *(const float4*)&Tsh[r][k];
        acc[r] = fmaf(t4.x,yv0, fmaf(t4.y,yv1, fmaf(t4.z,yv2, fmaf(t4.w,yv3, acc[r]))));
      }
    }
    __syncthreads();
  }
  float lm = blockSum256(lmain, red);
  if (tid==0) atomicAdd(&d_Lmain[b], lm);
  if (tid<32) d_r[b*NN + i0 + tid] = rsh[tid];
  float lb = 0.0f;
  const float* Xp = X + ((size_t)(b*NN + i0))*DD + tid;
  #pragma unroll
  for (int r=0;r<32;r++){
    float yb = acc[r] / (rsh[r] + 1e-8f);
    float diff = Xp[(size_t)r*DD] - yb;
    lb = fmaf(diff, diff, lb);
  }
  lb = blockSum256(lb, red);
  if (tid==0) atomicAdd(&d_LbX[b], lb);
}

// ------------ col pass: T^T@X, c_j, sum (Y - X_bar)^2 ------------------------
__global__ void __launch_bounds__(256) k_colpass(const float* __restrict__ X, const float* __restrict__ Y){
  __shared__ float fsh[NN];
  __shared__ float Tsh[64][36];
  __shared__ float csh[32];
  __shared__ float gshs[32];
  __shared__ float red[32];
  int b = blockIdx.y, j0 = blockIdx.x*32;
  int tid = threadIdx.x;
  for (int i=tid; i<NN; i+=256) fsh[i] = d_f[b*NN + i];
  if (tid<32){ csh[tid]=0.0f; gshs[tid]=d_g[b*NN + j0 + tid]; }
  __syncthreads();
  float acc[32];
  #pragma unroll
  for (int jj=0;jj<32;jj++) acc[jj]=0.0f;
  int jc = tid&31, r8 = (tid>>5)*8;
  const float* lkb = d_logK + (size_t)b*NN*NN + j0 + jc;
  const float* Xp  = X + (size_t)b*NN*DD + tid;
  float gv = gshs[jc];

  for (int ic=0; ic<NN; ic+=64){
    float cpart = 0.0f;
    #pragma unroll
    for (int u=0;u<8;u++){
      int i = ic + r8 + u;
      float lk = lkb[(size_t)i*NN];
      float t = exp2f((lk + fsh[i] + gv)*L2E);
      Tsh[r8+u][jc] = t;
      cpart += t;
    }
    atomicAdd(&csh[jc], cpart);
    __syncthreads();
    #pragma unroll 4
    for (int k=0;k<64;k++){
      float xv = Xp[(size_t)(ic+k)*DD];
      #pragma unroll
      for (int jj=0;jj<32;jj+=4){
        float4 t4 = *(const float4*)&Tsh[k][jj];
        acc[jj+0] = fmaf(t4.x, xv, acc[jj+0]);
        acc[jj+1] = fmaf(t4.y, xv, acc[jj+1]);
        acc[jj+2] = fmaf(t4.z, xv, acc[jj+2]);
        acc[jj+3] = fmaf(t4.w, xv, acc[jj+3]);
      }
    }
    __syncthreads();
  }
  if (tid<32) d_c[b*NN + j0 + tid] = csh[tid];
  float lb = 0.0f;
  const float* Yp = Y + ((size_t)(b*NN + j0))*DD + tid;
  #pragma unroll
  for (int jj=0;jj<32;jj++){
    float xb = acc[jj] / (csh[jj] + 1e-8f);
    float diff = Yp[(size_t)jj*DD] - xb;
    lb = fmaf(diff, diff, lb);
  }
  lb = blockSum256(lb, red);
  if (tid==0) atomicAdd(&d_LbY[b], lb);
}

// ------------ global-token cosine + per-batch loss combine -------------------
__global__ void __launch_bounds__(256) k_global(const float* __restrict__ X, const float* __restrict__ Y){
  __shared__ float red[32];
  int b = blockIdx.x, d = threadIdx.x;
  const float* Xp = X + (size_t)b*NN*DD + d;
  const float* Yp = Y + (size_t)b*NN*DD + d;
  const float* rp = d_r + b*NN;
  const float* cp = d_c + b*NN;
  float xg=0.0f, yg=0.0f, sr=0.0f, sc=0.0f;
  #pragma unroll 4
  for (int i=0;i<NN;i++){
    float rv = rp[i], cv = cp[i];
    xg = fmaf(Xp[(size_t)i*DD], rv, xg);
    yg = fmaf(Yp[(size_t)i*DD], cv, yg);
    sr += rv; sc += cv;
  }
  xg /= (sr + 1e-8f);
  yg /= (sc + 1e-8f);
  float ssx = blockSum256(xg*xg, red);
  float ssy = blockSum256(yg*yg, red);
  float ix = 1.0f / fmaxf(sqrtf(ssx), 1e-12f);
  float iy = 1.0f / fmaxf(sqrtf(ssy), 1e-12f);
  float dot = blockSum256((xg*ix)*(yg*iy), red);
  if (d==0){
    float lcos = 1.0f - dot;
    float lbary = (d_LbX[b] + d_LbY[b]) * (1.0f/((float)NN*(float)DD));
    d_loss[b] = d_Lmain[b] + 0.5f*lbary + 0.2f*lcos;
  }
}

__global__ void k_final(float* out){
  int t = threadIdx.x;
  float v = (t < BB) ? d_loss[t] : 0.0f;
  v = warpSum(v);
  if (t==0) out[0] = v * (1.0f/(float)BB);
}

extern "C" void kernel_launch(void* const* d_in, const int* in_sizes, int n_in,
                              void* d_out, int out_size) {
  const float* X = (const float*)d_in[0];   // eeg_embedding  (B,N,D)
  const float* Y = (const float*)d_in[1];   // text_embedding (B,N,D)
  float* out = (float*)d_out;
  (void)in_sizes; (void)n_in; (void)out_size;

  k_init<<<64, 256>>>();
  k_norms<<<dim3(BB*NN/8, 2), 256>>>(X, Y);
  k_gemm<<<dim3(NN/64, NN/64, BB), 256>>>(X, Y);
  for (int it=0; it<50; it++){
    k_f<<<BB*NN, 256>>>();
    k_g<<<dim3(NN/64, BB), 256>>>();
  }
  k_rowpass<<<dim3(NN/32, BB), 256>>>(X, Y);
  k_colpass<<<dim3(NN/32, BB), 256>>>(X, Y);
  k_global<<<BB, 256>>>(X, Y);
  k_final<<<1, 32>>>(out);
}

// round 2
// speedup vs baseline: 1.3222x; 1.3222x over previous
#include <cuda_runtime.h>
#include <math.h>
#include <stdint.h>

#define BB 16
#define NN 1024
#define DD 256
#define L2E 1.4426950408889634f

static __device__ float d_logK[BB*NN*NN];   // 64 MB scratch
static __device__ float d_f[BB*NN];
static __device__ float d_g[BB*NN];
static __device__ float d_inx[BB*NN];
static __device__ float d_iny[BB*NN];
static __device__ float d_r[BB*NN];
static __device__ float d_c[BB*NN];
static __device__ float d_Lmain[BB];
static __device__ float d_LbX[BB];
static __device__ float d_LbY[BB];
static __device__ float d_loss[BB];

__device__ __forceinline__ float warpMax(float v){
  #pragma unroll
  for (int o=16;o>0;o>>=1) v = fmaxf(v, __shfl_xor_sync(0xffffffffu, v, o));
  return v;
}
__device__ __forceinline__ float warpSum(float v){
  #pragma unroll
  for (int o=16;o>0;o>>=1) v += __shfl_xor_sync(0xffffffffu, v, o);
  return v;
}
__device__ __forceinline__ float blockSum256(float v, float* sm){
  __syncthreads();
  v = warpSum(v);
  int w = threadIdx.x>>5, l = threadIdx.x&31;
  if (l==0) sm[w]=v;
  __syncthreads();
  if (w==0){
    float t = (l<8)? sm[l] : 0.0f;
    t = warpSum(t);
    if (l==0) sm[0]=t;
  }
  __syncthreads();
  return sm[0];
}

// ---------------- init: zero g and loss accumulators (graph replays!) --------
__global__ void k_init(){
  int t = blockIdx.x*256 + threadIdx.x;
  for (int i=t; i<BB*NN; i += gridDim.x*256) d_g[i] = 0.0f;
  if (t < BB){ d_Lmain[t]=0.0f; d_LbX[t]=0.0f; d_LbY[t]=0.0f; }
}

// ---------------- inverse row norms (one warp per row) -----------------------
__global__ void __launch_bounds__(256) k_norms(const float* __restrict__ X, const float* __restrict__ Y){
  int warp = threadIdx.x>>5, lane = threadIdx.x&31;
  int row = blockIdx.x*8 + warp;               // 0..B*N-1
  const float* src = blockIdx.y ? Y : X;
  float* dst = blockIdx.y ? d_iny : d_inx;
  const float* p = src + (size_t)row*DD;
  float4 a = *(const float4*)(p + lane*4);
  float4 c = *(const float4*)(p + 128 + lane*4);
  float ss = a.x*a.x+a.y*a.y+a.z*a.z+a.w*a.w
           + c.x*c.x+c.y*c.y+c.z*c.z+c.w*c.w;
  ss = warpSum(ss);
  if (lane==0) dst[row] = 1.0f / fmaxf(sqrtf(ss), 1e-12f);
}

// ---------------- S = Xn Yn^T -> logK (64x64 tile, 4x4 microtile) ------------
__global__ void __launch_bounds__(256) k_gemm(const float* __restrict__ X, const float* __restrict__ Y){
  __shared__ float As[32][68];
  __shared__ float Bs[32][68];
  int b = blockIdx.z;
  int i0 = blockIdx.y*64, j0 = blockIdx.x*64;
  int tid = threadIdx.x;
  const float* Xp = X + ((size_t)(b*NN + i0))*DD;
  const float* Yp = Y + ((size_t)(b*NN + j0))*DD;
  int lrow = tid>>3, lk4 = (tid&7)*4;
  int tx = tid&15, ty = tid>>4;
  float acc[4][4];
  #pragma unroll
  for (int u=0;u<4;u++)
    #pragma unroll
    for (int w=0;w<4;w++) acc[u][w]=0.0f;

  for (int kc=0; kc<DD; kc+=32){
    #pragma unroll
    for (int h=0;h<2;h++){
      int r = lrow + h*32;
      float4 a = *(const float4*)(Xp + (size_t)r*DD + kc + lk4);
      As[lk4+0][r]=a.x; As[lk4+1][r]=a.y; As[lk4+2][r]=a.z; As[lk4+3][r]=a.w;
      float4 bv = *(const float4*)(Yp + (size_t)r*DD + kc + lk4);
      Bs[lk4+0][r]=bv.x; Bs[lk4+1][r]=bv.y; Bs[lk4+2][r]=bv.z; Bs[lk4+3][r]=bv.w;
    }
    __syncthreads();
    #pragma unroll
    for (int k=0;k<32;k++){
      float4 av = *(const float4*)&As[k][ty*4];
      float4 bv = *(const float4*)&Bs[k][tx*4];
      float a4[4]={av.x,av.y,av.z,av.w};
      float b4[4]={bv.x,bv.y,bv.z,bv.w};
      #pragma unroll
      for (int u=0;u<4;u++)
        #pragma unroll
        for (int w=0;w<4;w++)
          acc[u][w] = fmaf(a4[u], b4[w], acc[u][w]);
    }
    __syncthreads();
  }
  float inx[4], iny[4];
  #pragma unroll
  for (int u=0;u<4;u++){
    inx[u] = d_inx[b*NN + i0 + ty*4 + u];
    iny[u] = d_iny[b*NN + j0 + tx*4 + u];
  }
  #pragma unroll
  for (int u=0;u<4;u++){
    int i = i0 + ty*4 + u;
    float o[4];
    #pragma unroll
    for (int w=0;w<4;w++){
      int j = j0 + tx*4 + w;
      float S = acc[u][w]*inx[u]*iny[w];
      float q = fmaxf(1.0f - S, 0.0f);
      float pj = fabsf((float)(i-j))*(1.0f/1023.0f);
      o[w] = -100.0f*q - 0.2f*pj;          // logK = -C/eps
    }
    *(float4*)(d_logK + ((size_t)(b*NN+i))*NN + j0 + tx*4) = make_float4(o[0],o[1],o[2],o[3]);
  }
}

// ---------------- sinkhorn f-update: warp-per-row, no block barriers ---------
// f_i = loga - LSE_j(logK[i,:] + g_j)
__global__ void __launch_bounds__(256) k_f(){
  int warp = threadIdx.x>>5, lane = threadIdx.x&31;
  int row = blockIdx.x*8 + warp;          // = b*NN + i
  int b = row >> 10;
  const float4* lk = (const float4*)(d_logK + (size_t)row*NN);
  const float4* gp = (const float4*)(d_g + b*NN);
  float x[32];
  #pragma unroll
  for (int w=0;w<8;w++){
    int idx = w*32 + lane;                // float4 index 0..255
    float4 v  = lk[idx];
    float4 gv = gp[idx];
    x[w*4+0]=v.x+gv.x; x[w*4+1]=v.y+gv.y; x[w*4+2]=v.z+gv.z; x[w*4+3]=v.w+gv.w;
  }
  float m = -INFINITY;
  #pragma unroll
  for (int u=0;u<32;u++) m = fmaxf(m, x[u]);
  float M = warpMax(m);
  float s = 0.0f;
  #pragma unroll
  for (int u=0;u<32;u++) s += exp2f((x[u]-M)*L2E);
  float S = warpSum(s);
  if (lane==0){
    const float LOGA = logf(1.0f/(float)NN + 1e-12f);
    d_f[row] = LOGA - (M + logf(S));
  }
}

// ---------------- sinkhorn g-update: 16-col tiles, 1024 blocks ---------------
// g_j = logb - LSE_i(logK[:,j] + f_i)
__global__ void __launch_bounds__(256) k_g(){
  __shared__ float fsh[NN];
  __shared__ float msh[16][17];
  __shared__ float ssh[16][17];
  int b = blockIdx.y, j0 = blockIdx.x*16;
  int tid = threadIdx.x;
  for (int i=tid; i<NN; i+=256) fsh[i] = d_f[b*NN + i];
  __syncthreads();
  int jc = tid&15, ir = tid>>4;           // ir in 0..15
  const float* base = d_logK + (size_t)b*NN*NN + j0 + jc;
  float mm[4], ss[4];
  #pragma unroll
  for (int q=0;q<4;q++){ mm[q] = -INFINITY; ss[q] = 0.0f; }
  #pragma unroll 2
  for (int t=0; t<16; t++){
    #pragma unroll
    for (int q=0;q<4;q++){
      int i = ir + 16*(t*4 + q);
      float x = base[(size_t)i*NN] + fsh[i];
      if (x <= mm[q]) { ss[q] += exp2f((x-mm[q])*L2E); }
      else { ss[q] = fmaf(ss[q], exp2f((mm[q]-x)*L2E), 1.0f); mm[q] = x; }
    }
  }
  float M = fmaxf(fmaxf(mm[0],mm[1]), fmaxf(mm[2],mm[3]));
  float S = ss[0]*exp2f((mm[0]-M)*L2E) + ss[1]*exp2f((mm[1]-M)*L2E)
          + ss[2]*exp2f((mm[2]-M)*L2E) + ss[3]*exp2f((mm[3]-M)*L2E);
  msh[ir][jc] = M; ssh[ir][jc] = S;
  __syncthreads();
  if (tid < 16){
    int j = tid;
    float Mt = -INFINITY;
    #pragma unroll
    for (int r=0;r<16;r++) Mt = fmaxf(Mt, msh[r][j]);
    float St = 0.0f;
    #pragma unroll
    for (int r=0;r<16;r++) St += ssh[r][j]*exp2f((msh[r][j]-Mt)*L2E);
    const float LOGB = logf(1.0f/(float)NN + 1e-12f);
    d_g[b*NN + j0 + j] = LOGB - (Mt + logf(St));
  }
}

// ------------ row pass: T@Y, r_i, L_main, sum (X - Y_bar)^2 ------------------
__global__ void __launch_bounds__(256) k_rowpass(const float* __restrict__ X, const float* __restrict__ Y){
  __shared__ float gsh[NN];
  __shared__ float Tsh[32][68];
  __shared__ float rsh[32];
  __shared__ float fsh[32];
  __shared__ float red[32];
  int b = blockIdx.y, i0 = blockIdx.x*32;
  int tid = threadIdx.x;
  for (int j=tid; j<NN; j+=256) gsh[j] = d_g[b*NN + j];
  if (tid<32){ rsh[tid]=0.0f; fsh[tid]=d_f[b*NN + i0 + tid]; }
  __syncthreads();
  float acc[32];
  #pragma unroll
  for (int r=0;r<32;r++) acc[r]=0.0f;
  float lmain = 0.0f;
  int lr = tid>>3, lj8 = (tid&7)*8;
  const float* lkb = d_logK + ((size_t)(b*NN + i0))*NN;
  const float* Yp  = Y + ((size_t)b*NN)*DD + tid;

  for (int kc=0; kc<NN; kc+=64){
    float fv = fsh[lr];
    const float* rowp = lkb + (size_t)lr*NN + kc + lj8;
    float4 l0 = *(const float4*)rowp;
    float4 l1 = *(const float4*)(rowp+4);
    float lkv[8] = {l0.x,l0.y,l0.z,l0.w,l1.x,l1.y,l1.z,l1.w};
    float rpart = 0.0f;
    #pragma unroll
    for (int u=0;u<8;u++){
      int j = kc + lj8 + u;
      float t = exp2f((lkv[u] + fv + gsh[j])*L2E);     // T_ij
      Tsh[lr][lj8+u] = t;
      rpart += t;
      float pj = fabsf((float)(i0 + lr - j))*(1.0f/1023.0f);
      lmain = fmaf(t, (-lkv[u] - 0.2f*pj)*0.1f, lmain); // C_content recovered
    }
    atomicAdd(&rsh[lr], rpart);
    __syncthreads();
    #pragma unroll 4
    for (int k=0;k<64;k+=4){
      float yv0 = Yp[(size_t)(kc+k+0)*DD];
      float yv1 = Yp[(size_t)(kc+k+1)*DD];
      float yv2 = Yp[(size_t)(kc+k+2)*DD];
      float yv3 = Yp[(size_t)(kc+k+3)*DD];
      #pragma unroll
      for (int r=0;r<32;r++){
        float4 t4 = *(const float4*)&Tsh[r][k];
        acc[r] = fmaf(t4.x,yv0, fmaf(t4.y,yv1, fmaf(t4.z,yv2, fmaf(t4.w,yv3, acc[r]))));
      }
    }
    __syncthreads();
  }
  float lm = blockSum256(lmain, red);
  if (tid==0) atomicAdd(&d_Lmain[b], lm);
  if (tid<32) d_r[b*NN + i0 + tid] = rsh[tid];
  float lb = 0.0f;
  const float* Xp = X + ((size_t)(b*NN + i0))*DD + tid;
  #pragma unroll
  for (int r=0;r<32;r++){
    float yb = acc[r] / (rsh[r] + 1e-8f);
    float diff = Xp[(size_t)r*DD] - yb;
    lb = fmaf(diff, diff, lb);
  }
  lb = blockSum256(lb, red);
  if (tid==0) atomicAdd(&d_LbX[b], lb);
}

// ------------ col pass: T^T@X, c_j, sum (Y - X_bar)^2 ------------------------
__global__ void __launch_bounds__(256) k_colpass(const float* __restrict__ X, const float* __restrict__ Y){
  __shared__ float fsh[NN];
  __shared__ float Tsh[64][36];
  __shared__ float csh[32];
  __shared__ float gshs[32];
  __shared__ float red[32];
  int b = blockIdx.y, j0 = blockIdx.x*32;
  int tid = threadIdx.x;
  for (int i=tid; i<NN; i+=256) fsh[i] = d_f[b*NN + i];
  if (tid<32){ csh[tid]=0.0f; gshs[tid]=d_g[b*NN + j0 + tid]; }
  __syncthreads();
  float acc[32];
  #pragma unroll
  for (int jj=0;jj<32;jj++) acc[jj]=0.0f;
  int jc = tid&31, r8 = (tid>>5)*8;
  const float* lkb = d_logK + (size_t)b*NN*NN + j0 + jc;
  const float* Xp  = X + (size_t)b*NN*DD + tid;
  float gv = gshs[jc];

  for (int ic=0; ic<NN; ic+=64){
    float cpart = 0.0f;
    #pragma unroll
    for (int u=0;u<8;u++){
      int i = ic + r8 + u;
      float lk = lkb[(size_t)i*NN];
      float t = exp2f((lk + fsh[i] + gv)*L2E);
      Tsh[r8+u][jc] = t;
      cpart += t;
    }
    atomicAdd(&csh[jc], cpart);
    __syncthreads();
    #pragma unroll 4
    for (int k=0;k<64;k++){
      float xv = Xp[(size_t)(ic+k)*DD];
      #pragma unroll
      for (int jj=0;jj<32;jj+=4){
        float4 t4 = *(const float4*)&Tsh[k][jj];
        acc[jj+0] = fmaf(t4.x, xv, acc[jj+0]);
        acc[jj+1] = fmaf(t4.y, xv, acc[jj+1]);
        acc[jj+2] = fmaf(t4.z, xv, acc[jj+2]);
        acc[jj+3] = fmaf(t4.w, xv, acc[jj+3]);
      }
    }
    __syncthreads();
  }
  if (tid<32) d_c[b*NN + j0 + tid] = csh[tid];
  float lb = 0.0f;
  const float* Yp = Y + ((size_t)(b*NN + j0))*DD + tid;
  #pragma unroll
  for (int jj=0;jj<32;jj++){
    float xb = acc[jj] / (csh[jj] + 1e-8f);
    float diff = Yp[(size_t)jj*DD] - xb;
    lb = fmaf(diff, diff, lb);
  }
  lb = blockSum256(lb, red);
  if (tid==0) atomicAdd(&d_LbY[b], lb);
}

// ------------ global-token cosine + per-batch loss combine -------------------
__global__ void __launch_bounds__(256) k_global(const float* __restrict__ X, const float* __restrict__ Y){
  __shared__ float red[32];
  int b = blockIdx.x, d = threadIdx.x;
  const float* Xp = X + (size_t)b*NN*DD + d;
  const float* Yp = Y + (size_t)b*NN*DD + d;
  const float* rp = d_r + b*NN;
  const float* cp = d_c + b*NN;
  float xg=0.0f, yg=0.0f, sr=0.0f, sc=0.0f;
  #pragma unroll 4
  for (int i=0;i<NN;i++){
    float rv = rp[i], cv = cp[i];
    xg = fmaf(Xp[(size_t)i*DD], rv, xg);
    yg = fmaf(Yp[(size_t)i*DD], cv, yg);
    sr += rv; sc += cv;
  }
  xg /= (sr + 1e-8f);
  yg /= (sc + 1e-8f);
  float ssx = blockSum256(xg*xg, red);
  float ssy = blockSum256(yg*yg, red);
  float ix = 1.0f / fmaxf(sqrtf(ssx), 1e-12f);
  float iy = 1.0f / fmaxf(sqrtf(ssy), 1e-12f);
  float dot = blockSum256((xg*ix)*(yg*iy), red);
  if (d==0){
    float lcos = 1.0f - dot;
    float lbary = (d_LbX[b] + d_LbY[b]) * (1.0f/((float)NN*(float)DD));
    d_loss[b] = d_Lmain[b] + 0.5f*lbary + 0.2f*lcos;
  }
}

__global__ void k_final(float* out){
  int t = threadIdx.x;
  float v = (t < BB) ? d_loss[t] : 0.0f;
  v = warpSum(v);
  if (t==0) out[0] = v * (1.0f/(float)BB);
}

extern "C" void kernel_launch(void* const* d_in, const int* in_sizes, int n_in,
                              void* d_out, int out_size) {
  const float* X = (const float*)d_in[0];   // eeg_embedding  (B,N,D)
  const float* Y = (const float*)d_in[1];   // text_embedding (B,N,D)
  float* out = (float*)d_out;
  (void)in_sizes; (void)n_in; (void)out_size;

  k_init<<<64, 256>>>();
  k_norms<<<dim3(BB*NN/8, 2), 256>>>(X, Y);
  k_gemm<<<dim3(NN/64, NN/64, BB), 256>>>(X, Y);
  for (int it=0; it<50; it++){
    k_f<<<BB*NN/8, 256>>>();
    k_g<<<dim3(NN/16, BB), 256>>>();
  }
  k_rowpass<<<dim3(NN/32, BB), 256>>>(X, Y);
  k_colpass<<<dim3(NN/32, BB), 256>>>(X, Y);
  k_global<<<BB, 256>>>(X, Y);
  k_final<<<1, 32>>>(out);
}

// round 3
// speedup vs baseline: 1.4327x; 1.0836x over previous
#include <cuda_runtime.h>
#include <cuda_fp16.h>
#include <math.h>
#include <stdint.h>

#define BB 16
#define NN 1024
#define DD 256
#define L2E 1.4426950408889634f

static __device__ float  d_logK [BB*NN*NN];   // 64 MB fp32 row-major
static __device__ float  d_logKT[BB*NN*NN];   // 64 MB fp32 transposed
static __device__ __half d_logKh [BB*NN*NN];  // 32 MB fp16 row-major
static __device__ __half d_logKTh[BB*NN*NN];  // 32 MB fp16 transposed
static __device__ float d_f[BB*NN];
static __device__ float d_g[BB*NN];
static __device__ float d_inx[BB*NN];
static __device__ float d_iny[BB*NN];
static __device__ float d_r[BB*NN];
static __device__ float d_c[BB*NN];
static __device__ float d_Lmain[BB];
static __device__ float d_LbX[BB];
static __device__ float d_LbY[BB];
static __device__ float d_loss[BB];

__device__ __forceinline__ float warpMax(float v){
  #pragma unroll
  for (int o=16;o>0;o>>=1) v = fmaxf(v, __shfl_xor_sync(0xffffffffu, v, o));
  return v;
}
__device__ __forceinline__ float warpSum(float v){
  #pragma unroll
  for (int o=16;o>0;o>>=1) v += __shfl_xor_sync(0xffffffffu, v, o);
  return v;
}
__device__ __forceinline__ float blockSum256(float v, float* sm){
  __syncthreads();
  v = warpSum(v);
  int w = threadIdx.x>>5, l = threadIdx.x&31;
  if (l==0) sm[w]=v;
  __syncthreads();
  if (w==0){
    float t = (l<8)? sm[l] : 0.0f;
    t = warpSum(t);
    if (l==0) sm[0]=t;
  }
  __syncthreads();
  return sm[0];
}

__device__ __forceinline__ void fma2(unsigned long long& d, unsigned long long a, unsigned long long b){
  asm("fma.rn.f32x2 %0, %1, %2, %0;" : "+l"(d) : "l"(a), "l"(b));
}
__device__ __forceinline__ void unpack2(unsigned long long p, float& lo, float& hi){
  asm("mov.b64 {%0,%1}, %2;" : "=f"(lo), "=f"(hi) : "l"(p));
}

// ---------------- init: zero g and loss accumulators (graph replays!) --------
__global__ void k_init(){
  int t = blockIdx.x*256 + threadIdx.x;
  for (int i=t; i<BB*NN; i += gridDim.x*256) d_g[i] = 0.0f;
  if (t < BB){ d_Lmain[t]=0.0f; d_LbX[t]=0.0f; d_LbY[t]=0.0f; }
}

// ---------------- inverse row norms (one warp per row) -----------------------
__global__ void __launch_bounds__(256) k_norms(const float* __restrict__ X, const float* __restrict__ Y){
  int warp = threadIdx.x>>5, lane = threadIdx.x&31;
  int row = blockIdx.x*8 + warp;
  const float* src = blockIdx.y ? Y : X;
  float* dst = blockIdx.y ? d_iny : d_inx;
  const float* p = src + (size_t)row*DD;
  float4 a = *(const float4*)(p + lane*4);
  float4 c = *(const float4*)(p + 128 + lane*4);
  float ss = a.x*a.x+a.y*a.y+a.z*a.z+a.w*a.w
           + c.x*c.x+c.y*c.y+c.z*c.z+c.w*c.w;
  ss = warpSum(ss);
  if (lane==0) dst[row] = 1.0f / fmaxf(sqrtf(ss), 1e-12f);
}

// ------- S = Xn Yn^T -> logK (fp32 + fp16, row + transposed) -----------------
// 64x64 tile, 4x4 microtile, f32x2 packed FMAs (A duplicated in smem).
__global__ void __launch_bounds__(256) k_gemm(const float* __restrict__ X, const float* __restrict__ Y){
  __shared__ __align__(16) unsigned long long As2[32][68];  // (a,a) pairs, [k][row]
  __shared__ __align__(16) float Bs[32][68];                // [k][row]
  int b = blockIdx.z;
  int i0 = blockIdx.y*64, j0 = blockIdx.x*64;
  int tid = threadIdx.x;
  const float* Xp = X + ((size_t)(b*NN + i0))*DD;
  const float* Yp = Y + ((size_t)(b*NN + j0))*DD;
  int lrow = tid>>3, lk4 = (tid&7)*4;
  int tx = tid&15, ty = tid>>4;
  unsigned long long acc2[4][2];
  #pragma unroll
  for (int u=0;u<4;u++){ acc2[u][0]=0ull; acc2[u][1]=0ull; }

  for (int kc=0; kc<DD; kc+=32){
    #pragma unroll
    for (int h=0;h<2;h++){
      int r = lrow + h*32;
      float4 a = *(const float4*)(Xp + (size_t)r*DD + kc + lk4);
      *(float2*)&As2[lk4+0][r] = make_float2(a.x,a.x);
      *(float2*)&As2[lk4+1][r] = make_float2(a.y,a.y);
      *(float2*)&As2[lk4+2][r] = make_float2(a.z,a.z);
      *(float2*)&As2[lk4+3][r] = make_float2(a.w,a.w);
      float4 bv = *(const float4*)(Yp + (size_t)r*DD + kc + lk4);
      Bs[lk4+0][r]=bv.x; Bs[lk4+1][r]=bv.y; Bs[lk4+2][r]=bv.z; Bs[lk4+3][r]=bv.w;
    }
    __syncthreads();
    #pragma unroll
    for (int k=0;k<32;k++){
      unsigned long long a0 = As2[k][ty*4+0];
      unsigned long long a1 = As2[k][ty*4+1];
      unsigned long long a2 = As2[k][ty*4+2];
      unsigned long long a3 = As2[k][ty*4+3];
      unsigned long long b0 = *(const unsigned long long*)&Bs[k][tx*4];
      unsigned long long b1 = *(const unsigned long long*)&Bs[k][tx*4+2];
      fma2(acc2[0][0],a0,b0); fma2(acc2[0][1],a0,b1);
      fma2(acc2[1][0],a1,b0); fma2(acc2[1][1],a1,b1);
      fma2(acc2[2][0],a2,b0); fma2(acc2[2][1],a2,b1);
      fma2(acc2[3][0],a3,b0); fma2(acc2[3][1],a3,b1);
    }
    __syncthreads();
  }
  float acc[4][4];
  #pragma unroll
  for (int u=0;u<4;u++){
    unpack2(acc2[u][0], acc[u][0], acc[u][1]);
    unpack2(acc2[u][1], acc[u][2], acc[u][3]);
  }
  float inx[4], iny[4];
  #pragma unroll
  for (int u=0;u<4;u++){
    inx[u] = d_inx[b*NN + i0 + ty*4 + u];
    iny[u] = d_iny[b*NN + j0 + tx*4 + u];
  }
  float o[4][4];
  #pragma unroll
  for (int u=0;u<4;u++){
    int i = i0 + ty*4 + u;
    #pragma unroll
    for (int w=0;w<4;w++){
      int j = j0 + tx*4 + w;
      float S = acc[u][w]*inx[u]*iny[w];
      float q = fmaxf(1.0f - S, 0.0f);
      float pj = fabsf((float)(i-j))*(1.0f/1023.0f);
      o[u][w] = -100.0f*q - 0.2f*pj;          // logK = -C/eps
    }
    size_t off = ((size_t)(b*NN+i))*NN + j0 + tx*4;
    *(float4*)(d_logK + off) = make_float4(o[u][0],o[u][1],o[u][2],o[u][3]);
    __half2* hp = (__half2*)(d_logKh + off);
    hp[0] = __floats2half2_rn(o[u][0],o[u][1]);
    hp[1] = __floats2half2_rn(o[u][2],o[u][3]);
  }
  // ---- transposed writes via smem staging (reuse As2 as raw float buffer) ----
  float* tb = (float*)As2;          // need 64*65*4 = 16640B <= 17408B
  __syncthreads();
  #pragma unroll
  for (int u=0;u<4;u++)
    #pragma unroll
    for (int w=0;w<4;w++)
      tb[(tx*4+w)*65 + ty*4+u] = o[u][w];
  __syncthreads();
  int jl = tid>>2, seg = tid&3;
  size_t toff = ((size_t)(b*NN + j0 + jl))*NN + i0 + seg*16;
  #pragma unroll
  for (int h=0;h<4;h++){
    float v0 = tb[jl*65 + seg*16 + h*4 + 0];
    float v1 = tb[jl*65 + seg*16 + h*4 + 1];
    float v2 = tb[jl*65 + seg*16 + h*4 + 2];
    float v3 = tb[jl*65 + seg*16 + h*4 + 3];
    *(float4*)(d_logKT + toff + h*4) = make_float4(v0,v1,v2,v3);
    __half2* hp = (__half2*)(d_logKTh + toff + h*4);
    hp[0] = __floats2half2_rn(v0,v1);
    hp[1] = __floats2half2_rn(v2,v3);
  }
}

// ---------------- online LSE update (one exp per element) --------------------
__device__ __forceinline__ void olse(float x, float& m, float& s){
  float d = x - m;
  float e = exp2f(-fabsf(d)*L2E);
  if (d <= 0.0f) s += e;
  else { s = fmaf(s, e, 1.0f); m = x; }
}

// ---- sinkhorn half-iteration: out_row = log(1/N) - LSE_col(Mh[row,:] + pot) -
// MODE 0: f-update (Kh, pot=g, out=f).  MODE 1: g-update (KTh, pot=f, out=g).
template<int MODE>
__global__ void __launch_bounds__(256) k_lse(){
  int warp = threadIdx.x>>5, lane = threadIdx.x&31;
  int row = blockIdx.x*8 + warp;
  int b = row >> 10;
  const __half* Mh = MODE ? d_logKTh : d_logKh;
  const float* pot = MODE ? d_f : d_g;
  float* outp      = MODE ? d_g : d_f;
  const uint4*  mk = (const uint4*)(Mh + (size_t)row*NN);
  const float4* pp = (const float4*)(pot + b*NN);
  float m[4], s[4];
  #pragma unroll
  for (int q=0;q<4;q++){ m[q]=-INFINITY; s[q]=0.0f; }
  #pragma unroll
  for (int w=0;w<4;w++){
    int idx = w*32 + lane;                 // uint4 (8 halves) index
    uint4 kv = mk[idx];
    float4 g0 = pp[idx*2];
    float4 g1 = pp[idx*2+1];
    float2 ka = __half22float2(*(__half2*)&kv.x);
    float2 kb = __half22float2(*(__half2*)&kv.y);
    float2 kc = __half22float2(*(__half2*)&kv.z);
    float2 kd = __half22float2(*(__half2*)&kv.w);
    olse(ka.x+g0.x, m[0],s[0]); olse(ka.y+g0.y, m[1],s[1]);
    olse(kb.x+g0.z, m[2],s[2]); olse(kb.y+g0.w, m[3],s[3]);
    olse(kc.x+g1.x, m[0],s[0]); olse(kc.y+g1.y, m[1],s[1]);
    olse(kd.x+g1.z, m[2],s[2]); olse(kd.y+g1.w, m[3],s[3]);
  }
  float M = fmaxf(fmaxf(m[0],m[1]), fmaxf(m[2],m[3]));
  float S = s[0]*exp2f((m[0]-M)*L2E) + s[1]*exp2f((m[1]-M)*L2E)
          + s[2]*exp2f((m[2]-M)*L2E) + s[3]*exp2f((m[3]-M)*L2E);
  float Mw = warpMax(M);
  float Sw = warpSum(S*exp2f((M-Mw)*L2E));
  if (lane==0){
    const float LOGC = logf(1.0f/(float)NN + 1e-12f);
    outp[row] = LOGC - (Mw + logf(Sw));
  }
}

// ---- fused marginal pass (row-major streaming over M) -----------------------
// MAIN=1: rows=i over d_logK:  r_i, T@Y, L_main, sum(X-Y_bar)^2 -> d_r, d_LbX
// MAIN=0: rows=j over d_logKT: c_j, T^T@X,       sum(Y-X_bar)^2 -> d_c, d_LbY
template<int MAIN>
__global__ void __launch_bounds__(256) k_pass(const float* __restrict__ X, const float* __restrict__ Y){
  const float* M   = MAIN ? d_logK : d_logKT;
  const float* rpp = MAIN ? d_f : d_g;      // row potential
  const float* cpp = MAIN ? d_g : d_f;      // column potential
  const float* V   = MAIN ? Y : X;          // matvec source (indexed by col)
  const float* W   = MAIN ? X : Y;          // compare target (indexed by row)
  float* sum_out   = MAIN ? d_r : d_c;
  float* Lb_out    = MAIN ? d_LbX : d_LbY;

  __shared__ float csh[NN];
  __shared__ float Tsh[32][68];
  __shared__ float ssh[32];
  __shared__ float rsh[32];
  __shared__ float red[32];
  int b = blockIdx.y, i0 = blockIdx.x*32;
  int tid = threadIdx.x;
  for (int j=tid; j<NN; j+=256) csh[j] = cpp[b*NN + j];
  if (tid<32){ ssh[tid]=0.0f; rsh[tid]=rpp[b*NN + i0 + tid]; }
  __syncthreads();
  float acc[32];
  #pragma unroll
  for (int r=0;r<32;r++) acc[r]=0.0f;
  float lmain = 0.0f;
  int lr = tid>>3, lj8 = (tid&7)*8;
  const float* lkb = M + ((size_t)(b*NN + i0))*NN;
  const float* Vp  = V + ((size_t)b*NN)*DD + tid;

  for (int kc=0; kc<NN; kc+=64){
    float fv = rsh[lr];
    const float* rowp = lkb + (size_t)lr*NN + kc + lj8;
    float4 l0 = *(const float4*)rowp;
    float4 l1 = *(const float4*)(rowp+4);
    float lkv[8] = {l0.x,l0.y,l0.z,l0.w,l1.x,l1.y,l1.z,l1.w};
    float rpart = 0.0f;
    #pragma unroll
    for (int u=0;u<8;u++){
      int j = kc + lj8 + u;
      float t = exp2f((lkv[u] + fv + csh[j])*L2E);     // T entry
      Tsh[lr][lj8+u] = t;
      rpart += t;
      if (MAIN){
        float pj = fabsf((float)(i0 + lr - j))*(1.0f/1023.0f);
        lmain = fmaf(t, (-lkv[u] - 0.2f*pj)*0.1f, lmain); // T * C_content
      }
    }
    atomicAdd(&ssh[lr], rpart);
    __syncthreads();
    #pragma unroll 4
    for (int k=0;k<64;k+=4){
      float yv0 = Vp[(size_t)(kc+k+0)*DD];
      float yv1 = Vp[(size_t)(kc+k+1)*DD];
      float yv2 = Vp[(size_t)(kc+k+2)*DD];
      float yv3 = Vp[(size_t)(kc+k+3)*DD];
      #pragma unroll
      for (int r=0;r<32;r++){
        float4 t4 = *(const float4*)&Tsh[r][k];
        acc[r] = fmaf(t4.x,yv0, fmaf(t4.y,yv1, fmaf(t4.z,yv2, fmaf(t4.w,yv3, acc[r]))));
      }
    }
    __syncthreads();
  }
  if (MAIN){
    float lm = blockSum256(lmain, red);
    if (tid==0) atomicAdd(&d_Lmain[b], lm);
  }
  if (tid<32) sum_out[b*NN + i0 + tid] = ssh[tid];
  float lb = 0.0f;
  const float* Wp = W + ((size_t)(b*NN + i0))*DD + tid;
  #pragma unroll
  for (int r=0;r<32;r++){
    float yb = acc[r] / (ssh[r] + 1e-8f);
    float diff = Wp[(size_t)r*DD] - yb;
    lb = fmaf(diff, diff, lb);
  }
  lb = blockSum256(lb, red);
  if (tid==0) atomicAdd(Lb_out + b, lb);
}

// ------------ global-token cosine + per-batch loss combine -------------------
__global__ void __launch_bounds__(256) k_global(const float* __restrict__ X, const float* __restrict__ Y){
  __shared__ float red[32];
  int b = blockIdx.x, d = threadIdx.x;
  const float* Xp = X + (size_t)b*NN*DD + d;
  const float* Yp = Y + (size_t)b*NN*DD + d;
  const float* rp = d_r + b*NN;
  const float* cp = d_c + b*NN;
  float xg=0.0f, yg=0.0f, sr=0.0f, sc=0.0f;
  #pragma unroll 4
  for (int i=0;i<NN;i++){
    float rv = rp[i], cv = cp[i];
    xg = fmaf(Xp[(size_t)i*DD], rv, xg);
    yg = fmaf(Yp[(size_t)i*DD], cv, yg);
    sr += rv; sc += cv;
  }
  xg /= (sr + 1e-8f);
  yg /= (sc + 1e-8f);
  float ssx = blockSum256(xg*xg, red);
  float ssy = blockSum256(yg*yg, red);
  float ix = 1.0f / fmaxf(sqrtf(ssx), 1e-12f);
  float iy = 1.0f / fmaxf(sqrtf(ssy), 1e-12f);
  float dot = blockSum256((xg*ix)*(yg*iy), red);
  if (d==0){
    float lcos = 1.0f - dot;
    float lbary = (d_LbX[b] + d_LbY[b]) * (1.0f/((float)NN*(float)DD));
    d_loss[b] = d_Lmain[b] + 0.5f*lbary + 0.2f*lcos;
  }
}

__global__ void k_final(float* out){
  int t = threadIdx.x;
  float v = (t < BB) ? d_loss[t] : 0.0f;
  v = warpSum(v);
  if (t==0) out[0] = v * (1.0f/(float)BB);
}

extern "C" void kernel_launch(void* const* d_in, const int* in_sizes, int n_in,
                              void* d_out, int out_size) {
  const float* X = (const float*)d_in[0];   // eeg_embedding  (B,N,D)
  const float* Y = (const float*)d_in[1];   // text_embedding (B,N,D)
  float* out = (float*)d_out;
  (void)in_sizes; (void)n_in; (void)out_size;

  k_init<<<64, 256>>>();
  k_norms<<<dim3(BB*NN/8, 2), 256>>>(X, Y);
  k_gemm<<<dim3(NN/64, NN/64, BB), 256>>>(X, Y);
  for (int it=0; it<50; it++){
    k_lse<0><<<BB*NN/8, 256>>>();   // f-update from Kh  + g
    k_lse<1><<<BB*NN/8, 256>>>();   // g-update from KTh + f
  }
  k_pass<1><<<dim3(NN/32, BB), 256>>>(X, Y);   // rows: r, T@Y, L_main, LbX
  k_pass<0><<<dim3(NN/32, BB), 256>>>(X, Y);   // cols: c, T^T@X, LbY
  k_global<<<BB, 256>>>(X, Y);
  k_final<<<1, 32>>>(out);
}

// round 7
// speedup vs baseline: 1.6387x; 1.1437x over previous
#include <cuda_runtime.h>
#include <cuda_fp16.h>
#include <math.h>
#include <stdint.h>

#define BB 16
#define NN 1024
#define DD 256
#define L2E 1.4426950408889634f

// fp32 arrays: natural-log logK (row + transposed), used only by final passes.
static __device__ float  d_logK [BB*NN*NN];   // 64 MB
static __device__ float  d_logKT[BB*NN*NN];   // 64 MB
// fp16 arrays: logK * log2(e)  (log2 domain), used by the sinkhorn loop.
static __device__ __half d_logKh [BB*NN*NN];  // 32 MB
static __device__ __half d_logKTh[BB*NN*NN];  // 32 MB
// potentials in LOG2 domain (f2 = f*log2e)
static __device__ float  d_f[BB*NN];
static __device__ float  d_g[BB*NN];
static __device__ __half d_fh[BB*NN];
static __device__ __half d_gh[BB*NN];
static __device__ float d_inx[BB*NN];
static __device__ float d_iny[BB*NN];
static __device__ float d_r[BB*NN];
static __device__ float d_c[BB*NN];
static __device__ float d_Lmain[BB];
static __device__ float d_LbX[BB];
static __device__ float d_LbY[BB];
static __device__ float d_loss[BB];

__device__ __forceinline__ float warpMax(float v){
  #pragma unroll
  for (int o=16;o>0;o>>=1) v = fmaxf(v, __shfl_xor_sync(0xffffffffu, v, o));
  return v;
}
__device__ __forceinline__ float warpSum(float v){
  #pragma unroll
  for (int o=16;o>0;o>>=1) v += __shfl_xor_sync(0xffffffffu, v, o);
  return v;
}
__device__ __forceinline__ float blockSum256(float v, float* sm){
  __syncthreads();
  v = warpSum(v);
  int w = threadIdx.x>>5, l = threadIdx.x&31;
  if (l==0) sm[w]=v;
  __syncthreads();
  if (w==0){
    float t = (l<8)? sm[l] : 0.0f;
    t = warpSum(t);
    if (l==0) sm[0]=t;
  }
  __syncthreads();
  return sm[0];
}

__device__ __forceinline__ void fma2(unsigned long long& d, unsigned long long a, unsigned long long b){
  asm("fma.rn.f32x2 %0, %1, %2, %0;" : "+l"(d) : "l"(a), "l"(b));
}
__device__ __forceinline__ void unpack2(unsigned long long p, float& lo, float& hi){
  asm("mov.b64 {%0,%1}, %2;" : "=f"(lo), "=f"(hi) : "l"(p));
}

// ---------------- init: zero g (fp32 + fp16) and loss accumulators -----------
__global__ void k_init(){
  int t = blockIdx.x*256 + threadIdx.x;
  for (int i=t; i<BB*NN; i += gridDim.x*256){
    d_g[i] = 0.0f;
    d_gh[i] = __ushort_as_half((unsigned short)0);
  }
  if (t < BB){ d_Lmain[t]=0.0f; d_LbX[t]=0.0f; d_LbY[t]=0.0f; }
}

// ---------------- inverse row norms (one warp per row) -----------------------
__global__ void __launch_bounds__(256) k_norms(const float* __restrict__ X, const float* __restrict__ Y){
  int warp = threadIdx.x>>5, lane = threadIdx.x&31;
  int row = blockIdx.x*8 + warp;
  const float* src = blockIdx.y ? Y : X;
  float* dst = blockIdx.y ? d_iny : d_inx;
  const float* p = src + (size_t)row*DD;
  float4 a = *(const float4*)(p + lane*4);
  float4 c = *(const float4*)(p + 128 + lane*4);
  float ss = a.x*a.x+a.y*a.y+a.z*a.z+a.w*a.w
           + c.x*c.x+c.y*c.y+c.z*c.z+c.w*c.w;
  ss = warpSum(ss);
  if (lane==0) dst[row] = 1.0f / fmaxf(sqrtf(ss), 1e-12f);
}

// ------- S = Xn Yn^T -> logK (fp32 natural; fp16 log2-domain; row+T) ---------
__global__ void __launch_bounds__(256) k_gemm(const float* __restrict__ X, const float* __restrict__ Y){
  __shared__ __align__(16) unsigned long long As2[32][68];
  __shared__ __align__(16) float Bs[32][68];
  int b = blockIdx.z;
  int i0 = blockIdx.y*64, j0 = blockIdx.x*64;
  int tid = threadIdx.x;
  const float* Xp = X + ((size_t)(b*NN + i0))*DD;
  const float* Yp = Y + ((size_t)(b*NN + j0))*DD;
  int lrow = tid>>3, lk4 = (tid&7)*4;
  int tx = tid&15, ty = tid>>4;
  unsigned long long acc2[4][2];
  #pragma unroll
  for (int u=0;u<4;u++){ acc2[u][0]=0ull; acc2[u][1]=0ull; }

  for (int kc=0; kc<DD; kc+=32){
    #pragma unroll
    for (int h=0;h<2;h++){
      int r = lrow + h*32;
      float4 a = *(const float4*)(Xp + (size_t)r*DD + kc + lk4);
      *(float2*)&As2[lk4+0][r] = make_float2(a.x,a.x);
      *(float2*)&As2[lk4+1][r] = make_float2(a.y,a.y);
      *(float2*)&As2[lk4+2][r] = make_float2(a.z,a.z);
      *(float2*)&As2[lk4+3][r] = make_float2(a.w,a.w);
      float4 bv = *(const float4*)(Yp + (size_t)r*DD + kc + lk4);
      Bs[lk4+0][r]=bv.x; Bs[lk4+1][r]=bv.y; Bs[lk4+2][r]=bv.z; Bs[lk4+3][r]=bv.w;
    }
    __syncthreads();
    #pragma unroll
    for (int k=0;k<32;k++){
      unsigned long long a0 = As2[k][ty*4+0];
      unsigned long long a1 = As2[k][ty*4+1];
      unsigned long long a2 = As2[k][ty*4+2];
      unsigned long long a3 = As2[k][ty*4+3];
      unsigned long long b0 = *(const unsigned long long*)&Bs[k][tx*4];
      unsigned long long b1 = *(const unsigned long long*)&Bs[k][tx*4+2];
      fma2(acc2[0][0],a0,b0); fma2(acc2[0][1],a0,b1);
      fma2(acc2[1][0],a1,b0); fma2(acc2[1][1],a1,b1);
      fma2(acc2[2][0],a2,b0); fma2(acc2[2][1],a2,b1);
      fma2(acc2[3][0],a3,b0); fma2(acc2[3][1],a3,b1);
    }
    __syncthreads();
  }
  float acc[4][4];
  #pragma unroll
  for (int u=0;u<4;u++){
    unpack2(acc2[u][0], acc[u][0], acc[u][1]);
    unpack2(acc2[u][1], acc[u][2], acc[u][3]);
  }
  float inx[4], iny[4];
  #pragma unroll
  for (int u=0;u<4;u++){
    inx[u] = d_inx[b*NN + i0 + ty*4 + u];
    iny[u] = d_iny[b*NN + j0 + tx*4 + u];
  }
  float o[4][4];
  #pragma unroll
  for (int u=0;u<4;u++){
    int i = i0 + ty*4 + u;
    #pragma unroll
    for (int w=0;w<4;w++){
      int j = j0 + tx*4 + w;
      float S = acc[u][w]*inx[u]*iny[w];
      float q = fmaxf(1.0f - S, 0.0f);
      float pj = fabsf((float)(i-j))*(1.0f/1023.0f);
      o[u][w] = -100.0f*q - 0.2f*pj;          // logK = -C/eps (natural log)
    }
    size_t off = ((size_t)(b*NN+i))*NN + j0 + tx*4;
    *(float4*)(d_logK + off) = make_float4(o[u][0],o[u][1],o[u][2],o[u][3]);
    __half2* hp = (__half2*)(d_logKh + off);
    hp[0] = __floats2half2_rn(o[u][0]*L2E, o[u][1]*L2E);
    hp[1] = __floats2half2_rn(o[u][2]*L2E, o[u][3]*L2E);
  }
  // ---- transposed writes via smem staging ----
  float* tb = (float*)As2;
  __syncthreads();
  #pragma unroll
  for (int u=0;u<4;u++)
    #pragma unroll
    for (int w=0;w<4;w++)
      tb[(tx*4+w)*65 + ty*4+u] = o[u][w];
  __syncthreads();
  int jl = tid>>2, seg = tid&3;
  size_t toff = ((size_t)(b*NN + j0 + jl))*NN + i0 + seg*16;
  #pragma unroll
  for (int h=0;h<4;h++){
    float v0 = tb[jl*65 + seg*16 + h*4 + 0];
    float v1 = tb[jl*65 + seg*16 + h*4 + 1];
    float v2 = tb[jl*65 + seg*16 + h*4 + 2];
    float v3 = tb[jl*65 + seg*16 + h*4 + 3];
    *(float4*)(d_logKT + toff + h*4) = make_float4(v0,v1,v2,v3);
    __half2* hp = (__half2*)(d_logKTh + toff + h*4);
    hp[0] = __floats2half2_rn(v0*L2E, v1*L2E);
    hp[1] = __floats2half2_rn(v2*L2E, v3*L2E);
  }
}

// ---- sinkhorn half-iteration (log2 domain, packed half2) --------------------
// out_row = -10 - log2( sum_col 2^(Mh[row,:] + pot[col]) )
// MODE 0: f-update (Kh, pot=gh, out=f/fh).  MODE 1: g-update (KTh, pot=fh, out=g/gh).
template<int MODE>
__global__ void __launch_bounds__(256) k_lse(){
  int warp = threadIdx.x>>5, lane = threadIdx.x&31;
  int row = blockIdx.x*8 + warp;
  int b = row >> 10;
  const __half* Mh  = MODE ? d_logKTh : d_logKh;
  const __half* ph  = MODE ? d_fh : d_gh;
  float* outp       = MODE ? d_g : d_f;
  __half* outh      = MODE ? d_gh : d_fh;
  const uint4* mk = (const uint4*)(Mh + (size_t)row*NN);   // 128 uint4 per row
  const uint4* gk = (const uint4*)(ph + (size_t)b*NN);
  __half2 x[16];
  #pragma unroll
  for (int w=0;w<4;w++){
    int idx = w*32 + lane;
    uint4 kv = mk[idx];
    uint4 gv = gk[idx];
    x[w*4+0] = __hadd2(*(__half2*)&kv.x, *(__half2*)&gv.x);
    x[w*4+1] = __hadd2(*(__half2*)&kv.y, *(__half2*)&gv.y);
    x[w*4+2] = __hadd2(*(__half2*)&kv.z, *(__half2*)&gv.z);
    x[w*4+3] = __hadd2(*(__half2*)&kv.w, *(__half2*)&gv.w);
  }
  // max tree over 16 half2
  __half2 m01 = __hmax2(x[0],x[1]),   m23 = __hmax2(x[2],x[3]);
  __half2 m45 = __hmax2(x[4],x[5]),   m67 = __hmax2(x[6],x[7]);
  __half2 m89 = __hmax2(x[8],x[9]),   mab = __hmax2(x[10],x[11]);
  __half2 mcd = __hmax2(x[12],x[13]), mef = __hmax2(x[14],x[15]);
  __half2 ma = __hmax2(__hmax2(m01,m23), __hmax2(m45,m67));
  __half2 mb = __hmax2(__hmax2(m89,mab), __hmax2(mcd,mef));
  __half2 mm = __hmax2(ma, mb);
  float Ml = fmaxf(__low2float(mm), __high2float(mm));
  float Mw = warpMax(Ml);
  __half2 M2 = __float2half2_rn(Mw);
  // sum of 2^(x - M)
  __half2 s0 = h2exp2(__hsub2(x[0], M2));
  __half2 s1 = h2exp2(__hsub2(x[1], M2));
  __half2 s2 = h2exp2(__hsub2(x[2], M2));
  __half2 s3 = h2exp2(__hsub2(x[3], M2));
  #pragma unroll
  for (int q=4;q<16;q+=4){
    s0 = __hadd2(s0, h2exp2(__hsub2(x[q+0], M2)));
    s1 = __hadd2(s1, h2exp2(__hsub2(x[q+1], M2)));
    s2 = __hadd2(s2, h2exp2(__hsub2(x[q+2], M2)));
    s3 = __hadd2(s3, h2exp2(__hsub2(x[q+3], M2)));
  }
  float2 f0 = __half22float2(s0), f1 = __half22float2(s1);
  float2 f2 = __half22float2(s2), f3 = __half22float2(s3);
  float S = (f0.x+f0.y) + (f1.x+f1.y) + (f2.x+f2.y) + (f3.x+f3.y);
  float Sw = warpSum(S);
  if (lane==0){
    float out = -10.0f - (Mw + __log2f(Sw));   // log2(1/1024+1e-12) = -10 exactly
    outp[row] = out;
    outh[row] = __float2half_rn(out);
  }
}

// ---- fused marginal pass (row-major streaming over M; potentials log2) ------
template<int MAIN>
__global__ void __launch_bounds__(256) k_pass(const float* __restrict__ X, const float* __restrict__ Y){
  const float* M   = MAIN ? d_logK : d_logKT;
  const float* rpp = MAIN ? d_f : d_g;      // row potential (log2)
  const float* cpp = MAIN ? d_g : d_f;      // column potential (log2)
  const float* V   = MAIN ? Y : X;
  const float* W   = MAIN ? X : Y;
  float* sum_out   = MAIN ? d_r : d_c;
  float* Lb_out    = MAIN ? d_LbX : d_LbY;

  __shared__ float csh[NN];
  __shared__ float Tsh[32][68];
  __shared__ float ssh[32];
  __shared__ float rsh[32];
  __shared__ float red[32];
  int b = blockIdx.y, i0 = blockIdx.x*32;
  int tid = threadIdx.x;
  for (int j=tid; j<NN; j+=256) csh[j] = cpp[b*NN + j];
  if (tid<32){ ssh[tid]=0.0f; rsh[tid]=rpp[b*NN + i0 + tid]; }
  __syncthreads();
  float acc[32];
  #pragma unroll
  for (int r=0;r<32;r++) acc[r]=0.0f;
  float lmain = 0.0f;
  int lr = tid>>3, lj8 = (tid&7)*8;
  const float* lkb = M + ((size_t)(b*NN + i0))*NN;
  const float* Vp  = V + ((size_t)b*NN)*DD + tid;

  for (int kc=0; kc<NN; kc+=64){
    float fv = rsh[lr];
    const float* rowp = lkb + (size_t)lr*NN + kc + lj8;
    float4 l0 = *(const float4*)rowp;
    float4 l1 = *(const float4*)(rowp+4);
    float lkv[8] = {l0.x,l0.y,l0.z,l0.w,l1.x,l1.y,l1.z,l1.w};
    float rpart = 0.0f;
    #pragma unroll
    for (int u=0;u<8;u++){
      int j = kc + lj8 + u;
      float t = exp2f(fmaf(lkv[u], L2E, fv + csh[j]));   // T entry (potentials log2)
      Tsh[lr][lj8+u] = t;
      rpart += t;
      if (MAIN){
        float pj = fabsf((float)(i0 + lr - j))*(1.0f/1023.0f);
        lmain = fmaf(t, (-lkv[u] - 0.2f*pj)*0.1f, lmain);
      }
    }
    atomicAdd(&ssh[lr], rpart);
    __syncthreads();
    #pragma unroll 4
    for (int k=0;k<64;k+=4){
      float yv0 = Vp[(size_t)(kc+k+0)*DD];
      float yv1 = Vp[(size_t)(kc+k+1)*DD];
      float yv2 = Vp[(size_t)(kc+k+2)*DD];
      float yv3 = Vp[(size_t)(kc+k+3)*DD];
      #pragma unroll
      for (int r=0;r<32;r++){
        float4 t4 = *(const float4*)&Tsh[r][k];
        acc[r] = fmaf(t4.x,yv0, fmaf(t4.y,yv1, fmaf(t4.z,yv2, fmaf(t4.w,yv3, acc[r]))));
      }
    }
    __syncthreads();
  }
  if (MAIN){
    float lm = blockSum256(lmain, red);
    if (tid==0) atomicAdd(&d_Lmain[b], lm);
  }
  if (tid<32) sum_out[b*NN + i0 + tid] = ssh[tid];
  float lb = 0.0f;
  const float* Wp = W + ((size_t)(b*NN + i0))*DD + tid;
  #pragma unroll
  for (int r=0;r<32;r++){
    float yb = acc[r] / (ssh[r] + 1e-8f);
    float diff = Wp[(size_t)r*DD] - yb;
    lb = fmaf(diff, diff, lb);
  }
  lb = blockSum256(lb, red);
  if (tid==0) atomicAdd(Lb_out + b, lb);
}

// ------------ global-token cosine + per-batch loss combine -------------------
__global__ void __launch_bounds__(256) k_global(const float* __restrict__ X, const float* __restrict__ Y){
  __shared__ float red[32];
  int b = blockIdx.x, d = threadIdx.x;
  const float* Xp = X + (size_t)b*NN*DD + d;
  const float* Yp = Y + (size_t)b*NN*DD + d;
  const float* rp = d_r + b*NN;
  const float* cp = d_c + b*NN;
  float xg=0.0f, yg=0.0f, sr=0.0f, sc=0.0f;
  #pragma unroll 4
  for (int i=0;i<NN;i++){
    float rv = rp[i], cv = cp[i];
    xg = fmaf(Xp[(size_t)i*DD], rv, xg);
    yg = fmaf(Yp[(size_t)i*DD], cv, yg);
    sr += rv; sc += cv;
  }
  xg /= (sr + 1e-8f);
  yg /= (sc + 1e-8f);
  float ssx = blockSum256(xg*xg, red);
  float ssy = blockSum256(yg*yg, red);
  float ix = 1.0f / fmaxf(sqrtf(ssx), 1e-12f);
  float iy = 1.0f / fmaxf(sqrtf(ssy), 1e-12f);
  float dot = blockSum256((xg*ix)*(yg*iy), red);
  if (d==0){
    float lcos = 1.0f - dot;
    float lbary = (d_LbX[b] + d_LbY[b]) * (1.0f/((float)NN*(float)DD));
    d_loss[b] = d_Lmain[b] + 0.5f*lbary + 0.2f*lcos;
  }
}

__global__ void k_final(float* out){
  int t = threadIdx.x;
  float v = (t < BB) ? d_loss[t] : 0.0f;
  v = warpSum(v);
  if (t==0) out[0] = v * (1.0f/(float)BB);
}

extern "C" void kernel_launch(void* const* d_in, const int* in_sizes, int n_in,
                              void* d_out, int out_size) {
  const float* X = (const float*)d_in[0];   // eeg_embedding  (B,N,D)
  const float* Y = (const float*)d_in[1];   // text_embedding (B,N,D)
  float* out = (float*)d_out;
  (void)in_sizes; (void)n_in; (void)out_size;

  k_init<<<64, 256>>>();
  k_norms<<<dim3(BB*NN/8, 2), 256>>>(X, Y);
  k_gemm<<<dim3(NN/64, NN/64, BB), 256>>>(X, Y);
  for (int it=0; it<50; it++){
    k_lse<0><<<BB*NN/8, 256>>>();   // f-update from Kh  + g
    k_lse<1><<<BB*NN/8, 256>>>();   // g-update from KTh + f
  }
  k_pass<1><<<dim3(NN/32, BB), 256>>>(X, Y);   // rows: r, T@Y, L_main, LbX
  k_pass<0><<<dim3(NN/32, BB), 256>>>(X, Y);   // cols: c, T^T@X, LbY
  k_global<<<BB, 256>>>(X, Y);
  k_final<<<1, 32>>>(out);
}

// round 8
// speedup vs baseline: 1.8621x; 1.1363x over previous
#include <cuda_runtime.h>
#include <cuda_fp16.h>
#include <math.h>
#include <stdint.h>

#define BB 16
#define NN 1024
#define DD 256
#define L2E 1.4426950408889634f
#define LN2F 0.6931471805599453f

// fp16 arrays: logK * log2(e)  (log2 domain) — the ONLY K storage.
static __device__ __half d_logKh [BB*NN*NN];  // 32 MB
static __device__ __half d_logKTh[BB*NN*NN];  // 32 MB
// potentials in LOG2 domain
static __device__ float  d_f[BB*NN];
static __device__ float  d_g[BB*NN];
static __device__ __half d_fh[BB*NN];
static __device__ __half d_gh[BB*NN];
static __device__ float d_inx[BB*NN];
static __device__ float d_iny[BB*NN];
static __device__ float d_r[BB*NN];
static __device__ float d_c[BB*NN];
static __device__ float d_xg[BB*DD];
static __device__ float d_yg[BB*DD];
static __device__ float d_Lmain[BB];
static __device__ float d_LbX[BB];
static __device__ float d_LbY[BB];
static __device__ float d_loss[BB];

__device__ __forceinline__ float warpMax(float v){
  #pragma unroll
  for (int o=16;o>0;o>>=1) v = fmaxf(v, __shfl_xor_sync(0xffffffffu, v, o));
  return v;
}
__device__ __forceinline__ float warpSum(float v){
  #pragma unroll
  for (int o=16;o>0;o>>=1) v += __shfl_xor_sync(0xffffffffu, v, o);
  return v;
}
__device__ __forceinline__ float blockSum256(float v, float* sm){
  __syncthreads();
  v = warpSum(v);
  int w = threadIdx.x>>5, l = threadIdx.x&31;
  if (l==0) sm[w]=v;
  __syncthreads();
  if (w==0){
    float t = (l<8)? sm[l] : 0.0f;
    t = warpSum(t);
    if (l==0) sm[0]=t;
  }
  __syncthreads();
  return sm[0];
}

__device__ __forceinline__ void fma2(unsigned long long& d, unsigned long long a, unsigned long long b){
  asm("fma.rn.f32x2 %0, %1, %2, %0;" : "+l"(d) : "l"(a), "l"(b));
}
__device__ __forceinline__ void unpack2(unsigned long long p, float& lo, float& hi){
  asm("mov.b64 {%0,%1}, %2;" : "=f"(lo), "=f"(hi) : "l"(p));
}
__device__ __forceinline__ unsigned long long pack2(float lo, float hi){
  unsigned long long r;
  asm("mov.b64 %0, {%1,%2};" : "=l"(r) : "f"(lo), "f"(hi));
  return r;
}

// ---------------- init: zero accumulators (graph replays!) -------------------
__global__ void k_init(){
  int t = blockIdx.x*256 + threadIdx.x;
  for (int i=t; i<BB*NN; i += gridDim.x*256){
    d_g[i] = 0.0f;
    d_gh[i] = __ushort_as_half((unsigned short)0);
  }
  for (int i=t; i<BB*DD; i += gridDim.x*256){ d_xg[i]=0.0f; d_yg[i]=0.0f; }
  if (t < BB){ d_Lmain[t]=0.0f; d_LbX[t]=0.0f; d_LbY[t]=0.0f; }
}

// ---------------- inverse row norms (one warp per row) -----------------------
__global__ void __launch_bounds__(256) k_norms(const float* __restrict__ X, const float* __restrict__ Y){
  int warp = threadIdx.x>>5, lane = threadIdx.x&31;
  int row = blockIdx.x*8 + warp;
  const float* src = blockIdx.y ? Y : X;
  float* dst = blockIdx.y ? d_iny : d_inx;
  const float* p = src + (size_t)row*DD;
  float4 a = *(const float4*)(p + lane*4);
  float4 c = *(const float4*)(p + 128 + lane*4);
  float ss = a.x*a.x+a.y*a.y+a.z*a.z+a.w*a.w
           + c.x*c.x+c.y*c.y+c.z*c.z+c.w*c.w;
  ss = warpSum(ss);
  if (lane==0) dst[row] = 1.0f / fmaxf(sqrtf(ss), 1e-12f);
}

// ------- S = Xn Yn^T -> logKh (fp16 log2-domain, row + transposed) -----------
__global__ void __launch_bounds__(256) k_gemm(const float* __restrict__ X, const float* __restrict__ Y){
  __shared__ __align__(16) unsigned long long As2[32][68];
  __shared__ __align__(16) float Bs[32][68];
  int b = blockIdx.z;
  int i0 = blockIdx.y*64, j0 = blockIdx.x*64;
  int tid = threadIdx.x;
  const float* Xp = X + ((size_t)(b*NN + i0))*DD;
  const float* Yp = Y + ((size_t)(b*NN + j0))*DD;
  int lrow = tid>>3, lk4 = (tid&7)*4;
  int tx = tid&15, ty = tid>>4;
  unsigned long long acc2[4][2];
  #pragma unroll
  for (int u=0;u<4;u++){ acc2[u][0]=0ull; acc2[u][1]=0ull; }

  for (int kc=0; kc<DD; kc+=32){
    #pragma unroll
    for (int h=0;h<2;h++){
      int r = lrow + h*32;
      float4 a = *(const float4*)(Xp + (size_t)r*DD + kc + lk4);
      *(float2*)&As2[lk4+0][r] = make_float2(a.x,a.x);
      *(float2*)&As2[lk4+1][r] = make_float2(a.y,a.y);
      *(float2*)&As2[lk4+2][r] = make_float2(a.z,a.z);
      *(float2*)&As2[lk4+3][r] = make_float2(a.w,a.w);
      float4 bv = *(const float4*)(Yp + (size_t)r*DD + kc + lk4);
      Bs[lk4+0][r]=bv.x; Bs[lk4+1][r]=bv.y; Bs[lk4+2][r]=bv.z; Bs[lk4+3][r]=bv.w;
    }
    __syncthreads();
    #pragma unroll
    for (int k=0;k<32;k++){
      unsigned long long a0 = As2[k][ty*4+0];
      unsigned long long a1 = As2[k][ty*4+1];
      unsigned long long a2 = As2[k][ty*4+2];
      unsigned long long a3 = As2[k][ty*4+3];
      unsigned long long b0 = *(const unsigned long long*)&Bs[k][tx*4];
      unsigned long long b1 = *(const unsigned long long*)&Bs[k][tx*4+2];
      fma2(acc2[0][0],a0,b0); fma2(acc2[0][1],a0,b1);
      fma2(acc2[1][0],a1,b0); fma2(acc2[1][1],a1,b1);
      fma2(acc2[2][0],a2,b0); fma2(acc2[2][1],a2,b1);
      fma2(acc2[3][0],a3,b0); fma2(acc2[3][1],a3,b1);
    }
    __syncthreads();
  }
  float acc[4][4];
  #pragma unroll
  for (int u=0;u<4;u++){
    unpack2(acc2[u][0], acc[u][0], acc[u][1]);
    unpack2(acc2[u][1], acc[u][2], acc[u][3]);
  }
  float inx[4], iny[4];
  #pragma unroll
  for (int u=0;u<4;u++){
    inx[u] = d_inx[b*NN + i0 + ty*4 + u];
    iny[u] = d_iny[b*NN + j0 + tx*4 + u];
  }
  float o[4][4];
  #pragma unroll
  for (int u=0;u<4;u++){
    int i = i0 + ty*4 + u;
    #pragma unroll
    for (int w=0;w<4;w++){
      int j = j0 + tx*4 + w;
      float S = acc[u][w]*inx[u]*iny[w];
      float q = fmaxf(1.0f - S, 0.0f);
      float pj = fabsf((float)(i-j))*(1.0f/1023.0f);
      o[u][w] = (-100.0f*q - 0.2f*pj)*L2E;    // logK * log2e
    }
    size_t off = ((size_t)(b*NN+i))*NN + j0 + tx*4;
    __half2* hp = (__half2*)(d_logKh + off);
    hp[0] = __floats2half2_rn(o[u][0], o[u][1]);
    hp[1] = __floats2half2_rn(o[u][2], o[u][3]);
  }
  // ---- transposed fp16 writes via smem staging ----
  float* tb = (float*)As2;
  __syncthreads();
  #pragma unroll
  for (int u=0;u<4;u++)
    #pragma unroll
    for (int w=0;w<4;w++)
      tb[(tx*4+w)*65 + ty*4+u] = o[u][w];
  __syncthreads();
  int jl = tid>>2, seg = tid&3;
  size_t toff = ((size_t)(b*NN + j0 + jl))*NN + i0 + seg*16;
  #pragma unroll
  for (int h=0;h<4;h++){
    float v0 = tb[jl*65 + seg*16 + h*4 + 0];
    float v1 = tb[jl*65 + seg*16 + h*4 + 1];
    float v2 = tb[jl*65 + seg*16 + h*4 + 2];
    float v3 = tb[jl*65 + seg*16 + h*4 + 3];
    __half2* hp = (__half2*)(d_logKTh + toff + h*4);
    hp[0] = __floats2half2_rn(v0, v1);
    hp[1] = __floats2half2_rn(v2, v3);
  }
}

// ---- sinkhorn half-iteration (log2 domain, packed half2) --------------------
template<int MODE>
__global__ void __launch_bounds__(256) k_lse(){
  int warp = threadIdx.x>>5, lane = threadIdx.x&31;
  int row = blockIdx.x*8 + warp;
  int b = row >> 10;
  const __half* Mh  = MODE ? d_logKTh : d_logKh;
  const __half* ph  = MODE ? d_fh : d_gh;
  float* outp       = MODE ? d_g : d_f;
  __half* outh      = MODE ? d_gh : d_fh;
  const uint4* mk = (const uint4*)(Mh + (size_t)row*NN);
  const uint4* gk = (const uint4*)(ph + (size_t)b*NN);
  __half2 x[16];
  #pragma unroll
  for (int w=0;w<4;w++){
    int idx = w*32 + lane;
    uint4 kv = mk[idx];
    uint4 gv = gk[idx];
    x[w*4+0] = __hadd2(*(__half2*)&kv.x, *(__half2*)&gv.x);
    x[w*4+1] = __hadd2(*(__half2*)&kv.y, *(__half2*)&gv.y);
    x[w*4+2] = __hadd2(*(__half2*)&kv.z, *(__half2*)&gv.z);
    x[w*4+3] = __hadd2(*(__half2*)&kv.w, *(__half2*)&gv.w);
  }
  __half2 m01 = __hmax2(x[0],x[1]),   m23 = __hmax2(x[2],x[3]);
  __half2 m45 = __hmax2(x[4],x[5]),   m67 = __hmax2(x[6],x[7]);
  __half2 m89 = __hmax2(x[8],x[9]),   mab = __hmax2(x[10],x[11]);
  __half2 mcd = __hmax2(x[12],x[13]), mef = __hmax2(x[14],x[15]);
  __half2 ma = __hmax2(__hmax2(m01,m23), __hmax2(m45,m67));
  __half2 mb = __hmax2(__hmax2(m89,mab), __hmax2(mcd,mef));
  __half2 mm = __hmax2(ma, mb);
  float Ml = fmaxf(__low2float(mm), __high2float(mm));
  float Mw = warpMax(Ml);
  __half2 M2 = __float2half2_rn(Mw);
  __half2 s0 = h2exp2(__hsub2(x[0], M2));
  __half2 s1 = h2exp2(__hsub2(x[1], M2));
  __half2 s2 = h2exp2(__hsub2(x[2], M2));
  __half2 s3 = h2exp2(__hsub2(x[3], M2));
  #pragma unroll
  for (int q=4;q<16;q+=4){
    s0 = __hadd2(s0, h2exp2(__hsub2(x[q+0], M2)));
    s1 = __hadd2(s1, h2exp2(__hsub2(x[q+1], M2)));
    s2 = __hadd2(s2, h2exp2(__hsub2(x[q+2], M2)));
    s3 = __hadd2(s3, h2exp2(__hsub2(x[q+3], M2)));
  }
  float2 f0 = __half22float2(s0), f1 = __half22float2(s1);
  float2 f2 = __half22float2(s2), f3 = __half22float2(s3);
  float S = (f0.x+f0.y) + (f1.x+f1.y) + (f2.x+f2.y) + (f3.x+f3.y);
  float Sw = warpSum(S);
  if (lane==0){
    float out = -10.0f - (Mw + __log2f(Sw));
    outp[row] = out;
    outh[row] = __float2half_rn(out);
  }
}

// ---- fused marginal pass: fp16 K source, f32x2 matvec -----------------------
// MAIN=1: rows=i over Kh:  r_i, T@Y, L_main, sum(X-Y_bar)^2 -> d_r, d_LbX
// MAIN=0: rows=j over KTh: c_j, T^T@X,       sum(Y-X_bar)^2 -> d_c, d_LbY
template<int MAIN>
__global__ void __launch_bounds__(256) k_pass(const float* __restrict__ X, const float* __restrict__ Y){
  const __half* Mh = MAIN ? d_logKh : d_logKTh;
  const float* rpp = MAIN ? d_f : d_g;      // row potential (log2)
  const float* cpp = MAIN ? d_g : d_f;      // column potential (log2)
  const float* V   = MAIN ? Y : X;
  const float* W   = MAIN ? X : Y;
  float* sum_out   = MAIN ? d_r : d_c;
  float* Lb_out    = MAIN ? d_LbX : d_LbY;

  __shared__ float csh[NN];
  __shared__ __align__(16) float Tsh[64][36];   // [col][row], 16B-aligned rows
  __shared__ float ssh[32];
  __shared__ float rsh[32];
  __shared__ float red[32];
  int b = blockIdx.y, i0 = blockIdx.x*32;
  int tid = threadIdx.x;
  int lane = tid&31, wp = tid>>5;          // lane=row, wp=column-group
  for (int j=tid; j<NN; j+=256) csh[j] = cpp[b*NN + j];
  if (tid<32){ ssh[tid]=0.0f; rsh[tid]=rpp[b*NN + i0 + tid]; }
  __syncthreads();
  unsigned long long acc2[16];
  #pragma unroll
  for (int r=0;r<16;r++) acc2[r]=0ull;
  float lmain = 0.0f;
  const __half* lkb = Mh + ((size_t)(b*NN + i0))*NN;
  const float* Vp  = V + ((size_t)b*NN)*DD + tid;

  for (int kc=0; kc<NN; kc+=64){
    float fv = rsh[lane];
    uint4 kv = *(const uint4*)(lkb + (size_t)lane*NN + kc + wp*8);
    float2 p0 = __half22float2(*(__half2*)&kv.x);
    float2 p1 = __half22float2(*(__half2*)&kv.y);
    float2 p2 = __half22float2(*(__half2*)&kv.z);
    float2 p3 = __half22float2(*(__half2*)&kv.w);
    float lk2[8] = {p0.x,p0.y,p1.x,p1.y,p2.x,p2.y,p3.x,p3.y};
    float rpart = 0.0f;
    #pragma unroll
    for (int u=0;u<8;u++){
      int j = kc + wp*8 + u;
      float t = exp2f(lk2[u] + fv + csh[j]);      // T entry (all log2)
      Tsh[wp*8+u][lane] = t;
      rpart += t;
      if (MAIN){
        float pj = fabsf((float)(i0 + lane - j))*(1.0f/1023.0f);
        lmain = fmaf(t, (-lk2[u]*LN2F - 0.2f*pj)*0.1f, lmain);
      }
    }
    atomicAdd(&ssh[lane], rpart);
    __syncthreads();
    #pragma unroll 2
    for (int k=0;k<64;k++){
      float yv = Vp[(size_t)(kc+k)*DD];
      unsigned long long yv2 = pack2(yv, yv);
      const ulonglong2* trow = (const ulonglong2*)&Tsh[k][0];
      #pragma unroll
      for (int q=0;q<8;q++){
        ulonglong2 tv = trow[q];
        fma2(acc2[2*q+0], tv.x, yv2);
        fma2(acc2[2*q+1], tv.y, yv2);
      }
    }
    __syncthreads();
  }
  if (MAIN){
    float lm = blockSum256(lmain, red);
    if (tid==0) atomicAdd(&d_Lmain[b], lm);
  }
  if (tid<32) sum_out[b*NN + i0 + tid] = ssh[tid];
  float acc[32];
  #pragma unroll
  for (int r=0;r<16;r++) unpack2(acc2[r], acc[2*r], acc[2*r+1]);
  float lb = 0.0f;
  const float* Wp = W + ((size_t)(b*NN + i0))*DD + tid;
  #pragma unroll
  for (int r=0;r<32;r++){
    float yb = acc[r] / (ssh[r] + 1e-8f);
    float diff = Wp[(size_t)r*DD] - yb;
    lb = fmaf(diff, diff, lb);
  }
  lb = blockSum256(lb, red);
  if (tid==0) atomicAdd(Lb_out + b, lb);
}

// ------------ global token: partial weighted sums (parallel) -----------------
__global__ void __launch_bounds__(256) k_gpart(const float* __restrict__ X, const float* __restrict__ Y){
  int b = blockIdx.y, i0 = blockIdx.x*128;
  int d = threadIdx.x;
  const float* Xp = X + ((size_t)(b*NN + i0))*DD + d;
  const float* Yp = Y + ((size_t)(b*NN + i0))*DD + d;
  const float* rp = d_r + b*NN + i0;
  const float* cp = d_c + b*NN + i0;
  float xg=0.0f, yg=0.0f;
  #pragma unroll 4
  for (int i=0;i<128;i++){
    xg = fmaf(Xp[(size_t)i*DD], rp[i], xg);
    yg = fmaf(Yp[(size_t)i*DD], cp[i], yg);
  }
  atomicAdd(&d_xg[b*DD+d], xg);
  atomicAdd(&d_yg[b*DD+d], yg);
}

// ------------ global cosine + per-batch loss combine -------------------------
__global__ void __launch_bounds__(256) k_gfin(){
  __shared__ float red[32];
  int b = blockIdx.x, d = threadIdx.x;
  // sr, sc
  float srp = 0.0f, scp = 0.0f;
  #pragma unroll
  for (int q=0;q<4;q++){
    srp += d_r[b*NN + q*256 + d];
    scp += d_c[b*NN + q*256 + d];
  }
  float sr = blockSum256(srp, red);
  float sc = blockSum256(scp, red);
  float xg = d_xg[b*DD+d] / (sr + 1e-8f);
  float yg = d_yg[b*DD+d] / (sc + 1e-8f);
  float ssx = blockSum256(xg*xg, red);
  float ssy = blockSum256(yg*yg, red);
  float ix = 1.0f / fmaxf(sqrtf(ssx), 1e-12f);
  float iy = 1.0f / fmaxf(sqrtf(ssy), 1e-12f);
  float dot = blockSum256((xg*ix)*(yg*iy), red);
  if (d==0){
    float lcos = 1.0f - dot;
    float lbary = (d_LbX[b] + d_LbY[b]) * (1.0f/((float)NN*(float)DD));
    d_loss[b] = d_Lmain[b] + 0.5f*lbary + 0.2f*lcos;
  }
}

__global__ void k_final(float* out){
  int t = threadIdx.x;
  float v = (t < BB) ? d_loss[t] : 0.0f;
  v = warpSum(v);
  if (t==0) out[0] = v * (1.0f/(float)BB);
}

extern "C" void kernel_launch(void* const* d_in, const int* in_sizes, int n_in,
                              void* d_out, int out_size) {
  const float* X = (const float*)d_in[0];   // eeg_embedding  (B,N,D)
  const float* Y = (const float*)d_in[1];   // text_embedding (B,N,D)
  float* out = (float*)d_out;
  (void)in_sizes; (void)n_in; (void)out_size;

  k_init<<<64, 256>>>();
  k_norms<<<dim3(BB*NN/8, 2), 256>>>(X, Y);
  k_gemm<<<dim3(NN/64, NN/64, BB), 256>>>(X, Y);
  for (int it=0; it<50; it++){
    k_lse<0><<<BB*NN/8, 256>>>();   // f-update from Kh  + g
    k_lse<1><<<BB*NN/8, 256>>>();   // g-update from KTh + f
  }
  k_pass<1><<<dim3(NN/32, BB), 256>>>(X, Y);   // rows: r, T@Y, L_main, LbX
  k_pass<0><<<dim3(NN/32, BB), 256>>>(X, Y);   // cols: c, T^T@X, LbY
  k_gpart<<<dim3(NN/128, BB), 256>>>(X, Y);
  k_gfin<<<BB, 256>>>();
  k_final<<<1, 32>>>(out);
}